// round 12
// baseline (speedup 1.0000x reference)
#include <cuda_runtime.h>
#include <math.h>

#define NELEM  16384
#define KSEL   8192
#define NC     128
#define NT     128
#define NBINS  8192
#define BPT    (NBINS / NT)     // 64 bins per thread
#define SH     13
#define LOBITS 0x3B800000u      // float bits of 2^-8; lower scores clamp to bin 0

// ---- persistent scratch (zero-init at load; maintained across graph replays) ----
// hist + boundary counters double-buffered by launch parity: launch L uses [p=L&1],
// zeroes [p^1] during phase A (previous reader finished at the launch boundary).
__device__ __align__(16) unsigned int g_hist[2][NBINS];
__device__ uint2        g_cand[NELEM];
__device__ unsigned int g_ticket[2];
__device__ unsigned int g_done[2];
__device__ unsigned int g_launch;   // monotonic launch ticket (parity + barrier target)
__device__ unsigned int g_arrive;   // monotonic arrival counter (+NC per launch)

__device__ __forceinline__ unsigned int ld_acq(const unsigned int* p) {
    unsigned int v;
    asm volatile("ld.acquire.gpu.u32 %0, [%1];" : "=r"(v) : "l"(p) : "memory");
    return v;
}
__device__ __forceinline__ void red_rel_add(unsigned int* p, unsigned int v) {
    asm volatile("red.release.gpu.global.add.u32 [%0], %1;" :: "l"(p), "r"(v) : "memory");
}
__device__ __forceinline__ int score_bin(unsigned int v) {
    const int d = (int)(v - LOBITS);
    int bin = d < 0 ? 0 : (d >> SH);
    return bin < NBINS - 1 ? bin : NBINS - 1;
}

__global__ __launch_bounds__(NT, 1)
void connect_attention_wide(const float* __restrict__ x,
                            const float* __restrict__ w7,
                            float* __restrict__ out)
{
    __shared__ float        sx[NT + 6];
    __shared__ float        swt[7];
    __shared__ unsigned int sm_w[NT / 32];
    __shared__ unsigned int s_tick, s_w0, s_w1;

    const int tid  = threadIdx.x;
    const int lane = tid & 31;
    const int wid  = tid >> 5;
    const int E0   = (int)blockIdx.x * NT;
    const int gid  = E0 + tid;

    if (tid == 0) s_tick = atomicAdd(&g_launch, 1u);
    if (tid < 7)  swt[tid] = __ldg(w7 + tid);

    // ---- stage x tile (+3 halo each side) ----
    sx[3 + tid] = __ldg(x + gid);
    if (tid < 3) {
        const int gl = E0 - 3 + tid;
        sx[tid] = (gl >= 0) ? __ldg(x + gl) : 0.0f;
        const int gr = E0 + NT + tid;
        sx[3 + NT + tid] = (gr < NELEM) ? __ldg(x + gr) : 0.0f;
    }
    __syncthreads();

    const unsigned int L   = s_tick / NC;    // launch index (all CTAs agree)
    const unsigned int par = L & 1u;

    // ---- conv 'same' + sigmoid (accurate: selection must match reference) ----
    const float xi = sx[3 + tid];
    float y = sx[tid] * swt[0];
    y = fmaf(sx[tid + 1], swt[1], y);
    y = fmaf(sx[tid + 2], swt[2], y);
    y = fmaf(xi,          swt[3], y);
    y = fmaf(sx[tid + 4], swt[4], y);
    y = fmaf(sx[tid + 5], swt[5], y);
    y = fmaf(sx[tid + 6], swt[6], y);
    const float s = 1.0f / (1.0f + expf(-y));
    out[NELEM + gid] = s;                          // attention_score output

    const unsigned int v = __float_as_uint(s);     // positive: bit order == value order
    const int bin = score_bin(v);
    atomicAdd(&g_hist[par][bin], 1u);              // spread REDs

    // prepare NEXT launch's buffers (untouched during this launch)
    if (gid < NBINS) g_hist[par ^ 1u][gid] = 0u;   // first 8192 threads
    if (gid == 0) { g_ticket[par ^ 1u] = 0u; g_done[par ^ 1u] = 0u; }

    // ---- THE single grid sync: release-arrive + acquire-read polling ----
    __syncthreads();
    if (tid == 0) {
        __threadfence();                            // publish this CTA's REDs/stores
        red_rel_add(&g_arrive, 1u);
        const unsigned int target = (unsigned int)NC * (L + 1u);
        while (ld_acq(&g_arrive) < target) { }
    }
    __syncthreads();

    // ---- redundant per-CTA scan: 64 bins/thread, register resident ----
    const unsigned int* hist = g_hist[par];
    unsigned int h[BPT];
    {
        const uint4* hp = (const uint4*)(hist + tid * BPT);
        #pragma unroll
        for (int q = 0; q < BPT / 4; ++q) {        // 16 independent uint4 loads
            const uint4 u = __ldcg(hp + q);
            h[4 * q + 0] = u.x; h[4 * q + 1] = u.y;
            h[4 * q + 2] = u.z; h[4 * q + 3] = u.w;
        }
    }
    unsigned int local = 0;
    #pragma unroll
    for (int q = 0; q < BPT; ++q) local += h[q];

    // block exclusive scan (4 warps; all 32 lanes active in every shuffle)
    unsigned int inc = local;
    #pragma unroll
    for (int o = 1; o < 32; o <<= 1) {
        unsigned int t = __shfl_up_sync(0xffffffffu, inc, o);
        if (lane >= o) inc += t;
    }
    if (lane == 31) sm_w[wid] = inc;
    __syncthreads();
    if (wid == 0) {
        unsigned int wsum = (lane < NT / 32) ? sm_w[lane] : 0u;
        unsigned int winc = wsum;
        #pragma unroll
        for (int o = 1; o < 32; o <<= 1) {
            unsigned int t = __shfl_up_sync(0xffffffffu, winc, o);
            if (lane >= o) winc += t;
        }
        if (lane < NT / 32) sm_w[lane] = winc - wsum;   // exclusive warp base
    }
    __syncthreads();
    const unsigned int base = sm_w[wid] + inc - local;

    if (base < KSEL && base + local >= KSEL) {     // exactly one thread; regs only
        unsigned int c = base;
        #pragma unroll
        for (int q = 0; q < BPT; ++q) {
            if (c + h[q] >= KSEL) {
                s_w0 = (unsigned)(tid * BPT + q) | ((KSEL - c) << 16);  // bstar | jkeep<<16
                s_w1 = h[q];                                             // hcount
                break;
            }
            c += h[q];
        }
    }
    __syncthreads();
    const int          bstar  = (int)(s_w0 & 0xFFFFu);
    const unsigned int jkeep  = s_w0 >> 16;
    const unsigned int hcount = s_w1;

    // ---- emit from register-held x, s ----
    if (bin != bstar) {
        out[gid] = (bin < bstar) ? xi * (s + 1.0f) : 0.0f;
    } else {
        // register, release, wait for all hcount registrants, exact stable rank
        const unsigned int t = atomicAdd(&g_ticket[par], 1u);
        g_cand[t] = make_uint2(v, (unsigned int)gid);
        red_rel_add(&g_done[par], 1u);

        bool full = true;
        unsigned int spins = 0;
        while (ld_acq(&g_done[par]) < hcount) {
            if (++spins > (1u << 22)) { full = false; break; }   // safety valve
        }

        unsigned int rank = 0;
        if (full) {
            #pragma unroll 8
            for (unsigned int c = 0; c < hcount; ++c) {
                const uint2 cd = __ldcg(&g_cand[c]);
                rank += (cd.x < v) || (cd.x == v && cd.y < (unsigned int)gid);
            }
        } else {
            // fallback: exact rank from the stored score array (same result)
            for (int j = 0; j < NELEM; ++j) {
                const unsigned int vj = __float_as_uint(out[NELEM + j]);
                if (score_bin(vj) == bstar)
                    rank += (vj < v) || (vj == v && j < gid);
            }
        }
        out[gid] = (rank < jkeep) ? xi * (s + 1.0f) : 0.0f;
    }
}

extern "C" void kernel_launch(void* const* d_in, const int* in_sizes, int n_in,
                              void* d_out, int out_size)
{
    const float* x = (const float*)d_in[0];
    const float* w = (const float*)d_in[1];
    if (n_in >= 2 && in_sizes[0] == 7) {   // defensive input-order check
        const float* t = x; x = w; w = t;
    }
    float* out = (float*)d_out;

    connect_attention_wide<<<NC, NT>>>(x, w, out);
}

// round 13
// speedup vs baseline: 1.1348x; 1.1348x over previous
#include <cuda_runtime.h>
#include <math.h>

#define NELEM  16384
#define KSEL   8192
#define NC     16
#define NT     1024
#define NW     (NT / 32)
#define NBINS  16384
#define BPT    (NBINS / NT)     // 16 bins per thread
#define SH     12
#define LOBITS 0x3B800000u      // float bits of 2^-8; lower scores clamp to bin 0

// ---- persistent scratch (zero-init at load; maintained across graph replays) ----
// hist + boundary counters double-buffered by launch parity: launch L uses [p=L&1],
// zeroes [p^1] during phase A (its previous reader finished at the launch boundary).
__device__ __align__(16) unsigned int g_hist[2][NBINS];
__device__ uint2        g_cand[NELEM];
__device__ unsigned int g_ticket[2];
__device__ unsigned int g_done[2];
__device__ unsigned int g_launch;   // monotonic launch ticket (parity + barrier target)
__device__ unsigned int g_arrive;   // monotonic arrival counter (+NC per launch)

__device__ __forceinline__ unsigned int ld_acq(const unsigned int* p) {
    unsigned int v;
    asm volatile("ld.acquire.gpu.u32 %0, [%1];" : "=r"(v) : "l"(p) : "memory");
    return v;
}
__device__ __forceinline__ void red_rel_add(unsigned int* p, unsigned int v) {
    asm volatile("red.release.gpu.global.add.u32 [%0], %1;" :: "l"(p), "r"(v) : "memory");
}
__device__ __forceinline__ int score_bin(unsigned int v) {
    const int d = (int)(v - LOBITS);
    int bin = d < 0 ? 0 : (d >> SH);
    return bin < NBINS - 1 ? bin : NBINS - 1;
}

__global__ __launch_bounds__(NT, 1)
void connect_attention_16(const float* __restrict__ x,
                          const float* __restrict__ w7,
                          float* __restrict__ out)
{
    __shared__ float        sx[NT + 6];
    __shared__ float        swt[7];
    __shared__ unsigned int sm_w[NW];
    __shared__ unsigned int s_tick, s_w0, s_w1;

    const int tid  = threadIdx.x;
    const int lane = tid & 31;
    const int wid  = tid >> 5;
    const int E0   = (int)blockIdx.x * NT;
    const int gid  = E0 + tid;

    if (tid == 0) s_tick = atomicAdd(&g_launch, 1u);
    if (tid < 7)  swt[tid] = __ldg(w7 + tid);

    // ---- stage x tile (+3 halo each side) ----
    sx[3 + tid] = __ldg(x + gid);
    if (tid < 3) {
        const int gl = E0 - 3 + tid;
        sx[tid] = (gl >= 0) ? __ldg(x + gl) : 0.0f;
        const int gr = E0 + NT + tid;
        sx[3 + NT + tid] = (gr < NELEM) ? __ldg(x + gr) : 0.0f;
    }
    __syncthreads();

    const unsigned int L   = s_tick / NC;     // launch index (all CTAs agree)
    const unsigned int par = L & 1u;

    // ---- conv 'same' + sigmoid (accurate expf: protects selection boundary) ----
    const float xi = sx[3 + tid];
    float y = sx[tid] * swt[0];
    y = fmaf(sx[tid + 1], swt[1], y);
    y = fmaf(sx[tid + 2], swt[2], y);
    y = fmaf(xi,          swt[3], y);
    y = fmaf(sx[tid + 4], swt[4], y);
    y = fmaf(sx[tid + 5], swt[5], y);
    y = fmaf(sx[tid + 6], swt[6], y);
    const float s = 1.0f / (1.0f + expf(-y));
    out[NELEM + gid] = s;                           // attention_score output

    const unsigned int v = __float_as_uint(s);      // positive: bit order == value order
    const int bin = score_bin(v);
    atomicAdd(&g_hist[par][bin], 1u);               // spread REDs

    // prepare NEXT launch's buffers (untouched during this launch)
    g_hist[par ^ 1u][gid] = 0u;                     // 16384 threads cover all bins
    if (gid == 0) { g_ticket[par ^ 1u] = 0u; g_done[par ^ 1u] = 0u; }

    // ---- single grid sync: 16 release-RMWs + acquire-READ polling ----
    __syncthreads();
    if (tid == 0) {
        __threadfence();                             // publish this CTA's REDs
        red_rel_add(&g_arrive, 1u);
        const unsigned int target = (unsigned int)NC * (L + 1u);
        while (ld_acq(&g_arrive) < target) { }
    }
    __syncthreads();

    // ---- redundant per-CTA scan: 16 bins/thread, register resident ----
    const unsigned int* hist = g_hist[par];
    unsigned int h[BPT];
    {
        const uint4* hp = (const uint4*)(hist + tid * BPT);
        const uint4 q0 = __ldcg(hp + 0), q1 = __ldcg(hp + 1),
                    q2 = __ldcg(hp + 2), q3 = __ldcg(hp + 3);
        h[0]=q0.x;  h[1]=q0.y;  h[2]=q0.z;  h[3]=q0.w;
        h[4]=q1.x;  h[5]=q1.y;  h[6]=q1.z;  h[7]=q1.w;
        h[8]=q2.x;  h[9]=q2.y;  h[10]=q2.z; h[11]=q2.w;
        h[12]=q3.x; h[13]=q3.y; h[14]=q3.z; h[15]=q3.w;
    }
    unsigned int local = 0;
    #pragma unroll
    for (int q = 0; q < BPT; ++q) local += h[q];

    // block exclusive scan (32 warps; all 32 lanes active in every shuffle)
    unsigned int inc = local;
    #pragma unroll
    for (int o = 1; o < 32; o <<= 1) {
        unsigned int t = __shfl_up_sync(0xffffffffu, inc, o);
        if (lane >= o) inc += t;
    }
    if (lane == 31) sm_w[wid] = inc;
    __syncthreads();
    if (wid == 0) {
        unsigned int wsum = sm_w[lane];              // NW == 32
        unsigned int winc = wsum;
        #pragma unroll
        for (int o = 1; o < 32; o <<= 1) {
            unsigned int t = __shfl_up_sync(0xffffffffu, winc, o);
            if (lane >= o) winc += t;
        }
        sm_w[lane] = winc - wsum;                    // exclusive warp base
    }
    __syncthreads();
    const unsigned int base = sm_w[wid] + inc - local;

    if (base < KSEL && base + local >= KSEL) {       // exactly one thread; regs only
        unsigned int c = base;
        #pragma unroll
        for (int q = 0; q < BPT; ++q) {
            if (c + h[q] >= KSEL) {
                s_w0 = (unsigned)(tid * BPT + q) | ((KSEL - c) << 16);  // bstar|jkeep<<16
                s_w1 = h[q];                                             // hcount
                break;
            }
            c += h[q];
        }
    }
    __syncthreads();
    const int          bstar  = (int)(s_w0 & 0xFFFFu);
    const unsigned int jkeep  = s_w0 >> 16;
    const unsigned int hcount = s_w1;

    // ---- emit from register-held x, s ----
    if (bin != bstar) {
        out[gid] = (bin < bstar) ? xi * (s + 1.0f) : 0.0f;
    } else {
        // register, release, wait for all hcount registrants, exact stable rank
        const unsigned int t = atomicAdd(&g_ticket[par], 1u);
        g_cand[t] = make_uint2(v, (unsigned int)gid);
        red_rel_add(&g_done[par], 1u);

        bool full = true;
        unsigned int spins = 0;
        while (ld_acq(&g_done[par]) < hcount) {
            if (++spins > (1u << 22)) { full = false; break; }   // safety valve
        }

        unsigned int rank = 0;
        if (full) {
            for (unsigned int c = 0; c < hcount; ++c) {
                const uint2 cd = __ldcg(&g_cand[c]);
                rank += (cd.x < v) || (cd.x == v && cd.y < (unsigned int)gid);
            }
        } else {
            // fallback: exact rank from the stored score array (same result)
            for (int j = 0; j < NELEM; ++j) {
                const unsigned int vj = __float_as_uint(out[NELEM + j]);
                if (score_bin(vj) == bstar)
                    rank += (vj < v) || (vj == v && j < gid);
            }
        }
        out[gid] = (rank < jkeep) ? xi * (s + 1.0f) : 0.0f;
    }
}

extern "C" void kernel_launch(void* const* d_in, const int* in_sizes, int n_in,
                              void* d_out, int out_size)
{
    const float* x = (const float*)d_in[0];
    const float* w = (const float*)d_in[1];
    if (n_in >= 2 && in_sizes[0] == 7) {   // defensive input-order check
        const float* t = x; x = w; w = t;
    }
    float* out = (float*)d_out;

    connect_attention_16<<<NC, NT>>>(x, w, out);
}